// round 16
// baseline (speedup 1.0000x reference)
#include <cuda_runtime.h>
#include <cstdint>

#define B_ 256
#define T_ 1024
#define D_ 64
#define H_ 100
#define G_ 400   // 4*H
#define TT 256   // t-tile per xg block
#define L2E 1.44269504088896f

// Precomputed input-gate contributions, PERMUTED row order:
// xg[b][t][p] holds gate-row ((p&3)*H + (p>>2)), bias included.  ~419 MB.
__device__ float g_xg[(size_t)B_ * T_ * G_];

// ---------------------------------------------------------------------------
// Packed f32x2 helpers
// ---------------------------------------------------------------------------
__device__ __forceinline__ unsigned long long ffma2(unsigned long long a,
                                                    unsigned long long b,
                                                    unsigned long long c) {
    unsigned long long d;
    asm("fma.rn.f32x2 %0, %1, %2, %3;" : "=l"(d) : "l"(a), "l"(b), "l"(c));
    return d;
}
__device__ __forceinline__ unsigned long long add2(unsigned long long a,
                                                   unsigned long long b) {
    unsigned long long d;
    asm("add.rn.f32x2 %0, %1, %2;" : "=l"(d) : "l"(a), "l"(b));
    return d;
}
__device__ __forceinline__ unsigned long long pack2(float x, float y) {
    return ((unsigned long long)__float_as_uint(y) << 32) |
           (unsigned long long)__float_as_uint(x);
}
__device__ __forceinline__ float lo2(unsigned long long v) {
    return __uint_as_float((unsigned)v);
}
__device__ __forceinline__ float hi2(unsigned long long v) {
    return __uint_as_float((unsigned)(v >> 32));
}
__device__ __forceinline__ float ex2a(float x) {
    float r; asm("ex2.approx.ftz.f32 %0, %1;" : "=f"(r) : "f"(x)); return r;
}
__device__ __forceinline__ float rcpa(float x) {
    float r; asm("rcp.approx.ftz.f32 %0, %1;" : "=f"(r) : "f"(x)); return r;
}
// sigmoid(x) = 1 - 1/(e^x+1)  (lm=log2e, s=1);  tanh(x) = 1 - 2/(e^2x+1)
__device__ __forceinline__ float uact(float x, float lm, float s) {
    return 1.0f - s * rcpa(ex2a(lm * x) + 1.0f);
}

// ---------------------------------------------------------------------------
// Kernel 1: xg — R13 version VERBATIM (local optimum: 484 us).
// ---------------------------------------------------------------------------
__global__ __launch_bounds__(512, 1)
void xg_kernel(const float* __restrict__ x,
               const float* __restrict__ W_ih,
               const float* __restrict__ b_ih,
               const float* __restrict__ b_hh) {
    extern __shared__ ulonglong2 xs[];  // [TT][16] : 256 t x 64 k fp32 (64 KB)

    const int b   = blockIdx.y;
    const int t0  = blockIdx.x * TT;
    const int tid = threadIdx.x;

    {   // coalesced float4 tile load: TT*16 = 4096 chunks / 512 threads
        const float4* src = (const float4*)(x + ((size_t)b * T_ + t0) * D_);
        float4* dst = (float4*)xs;
#pragma unroll
        for (int it = 0; it < TT * 16 / 512; it++)
            dst[tid + it * 512] = src[tid + it * 512];
    }

    unsigned long long w2[32];
    float bias = 0.0f;
    if (tid < G_) {
        const int row = (tid & 3) * H_ + (tid >> 2);
        const float4* wrow = (const float4*)(W_ih + (size_t)row * D_);
#pragma unroll
        for (int i = 0; i < 16; i++) {
            float4 v = wrow[i];
            w2[2 * i]     = pack2(v.x, v.y);
            w2[2 * i + 1] = pack2(v.z, v.w);
        }
        bias = b_ih[row] + b_hh[row];
    }
    __syncthreads();

    if (tid < G_) {
        float* out = g_xg + ((size_t)b * T_ + t0) * G_ + tid;
#pragma unroll 2
        for (int t = 0; t < TT; t++) {
            unsigned long long a0 = 0ull, a1 = 0ull;
#pragma unroll
            for (int i = 0; i < 16; i++) {
                ulonglong2 xv = xs[t * 16 + i];    // broadcast LDS.128
                a0 = ffma2(w2[2 * i],     xv.x, a0);
                a1 = ffma2(w2[2 * i + 1], xv.y, a1);
            }
            unsigned long long s2 = add2(a0, a1);
            out[(size_t)t * G_] = lo2(s2) + hi2(s2) + bias;
        }
    }
}

// ---------------------------------------------------------------------------
// Kernel 2: recurrence — R13 layout (416 thr, 13 warps, W row in 50 regs)
// with phase B folded into the quad via shuffles: gates {i,f,g,o} of unit j
// live in lanes 4j..4j+3, so after activation 6 quad-local shfl deliver
// f,g,o (both batches) to the gate-0 lane, which owns c and writes h into
// the OTHER hs buffer. ONE __syncthreads per step; gbuf eliminated.
// ---------------------------------------------------------------------------
__global__ __launch_bounds__(416, 1)
void lstm_kernel(const float* __restrict__ h0,
                 const float* __restrict__ c0,
                 const float* __restrict__ W_hh,
                 const float* __restrict__ W_fc,
                 const float* __restrict__ b_fc,
                 float* __restrict__ out) {
    __shared__ ulonglong2 hs[2][2][25];  // [buf][batch][100 floats]
    __shared__ float wfc_s[H_];

    const int tid    = threadIdx.x;
    const int batch0 = blockIdx.x * 2;
    const int gate   = tid & 3;
    const int j      = tid >> 2;
    const int lane   = tid & 31;
    const unsigned qmask = 0xFu << (lane & 28);
    const int lq     = lane & 28;        // quad base lane

    // init h buffer 0
    if (tid < 2 * H_) {
        const int b = tid / H_, jj = tid - b * H_;
        ((float*)hs[0][b])[jj] = h0[(size_t)(batch0 + b) * H_ + jj];
    }
    if (tid < H_) wfc_s[tid] = W_fc[tid];

    unsigned long long w2[50];
    float lm = L2E, sc = 1.0f;
    float cr0 = 0.0f, cr1 = 0.0f;        // cell state (gate-0 lanes only)
    if (tid < G_) {
        const int row = gate * H_ + j;
        const float4* wrow = (const float4*)(W_hh + (size_t)row * H_);
#pragma unroll
        for (int i = 0; i < 25; i++) {
            float4 v = wrow[i];
            w2[2 * i]     = pack2(v.x, v.y);
            w2[2 * i + 1] = pack2(v.z, v.w);
        }
        if (gate == 2) { lm = 2.0f * L2E; sc = 2.0f; }
        cr0 = c0[(size_t)(batch0)     * H_ + j];
        cr1 = c0[(size_t)(batch0 + 1) * H_ + j];
    }

    const float* xg0 = g_xg + (size_t)(batch0)     * T_ * G_ + tid;
    const float* xg1 = g_xg + (size_t)(batch0 + 1) * T_ * G_ + tid;
    float xgc0 = 0.0f, xgc1 = 0.0f;
    if (tid < G_) { xgc0 = xg0[0]; xgc1 = xg1[0]; }

    __syncthreads();

    int cur = 0;
    for (int t = 0; t < T_; t++) {
        float xgn0 = 0.0f, xgn1 = 0.0f;
        if (tid < G_ && t + 1 < T_) {
            xgn0 = xg0[(size_t)(t + 1) * G_];
            xgn1 = xg1[(size_t)(t + 1) * G_];
        }

        if (tid < G_) {
            unsigned long long a0 = 0ull, a1 = 0ull, b0 = 0ull, b1 = 0ull;
#pragma unroll
            for (int i = 0; i < 25; i++) {
                ulonglong2 hv = hs[cur][0][i];     // broadcast LDS.128
                a0 = ffma2(w2[2 * i],     hv.x, a0);
                a1 = ffma2(w2[2 * i + 1], hv.y, a1);
            }
#pragma unroll
            for (int i = 0; i < 25; i++) {
                ulonglong2 hv = hs[cur][1][i];
                b0 = ffma2(w2[2 * i],     hv.x, b0);
                b1 = ffma2(w2[2 * i + 1], hv.y, b1);
            }
            float acc0 = lo2(a0) + hi2(a0) + lo2(a1) + hi2(a1) + xgc0;
            float acc1 = lo2(b0) + hi2(b0) + lo2(b1) + hi2(b1) + xgc1;

            // branch-free activation: my gate, both batches
            float r0 = uact(acc0, lm, sc);
            float r1 = uact(acc1, lm, sc);

            // quad gather: f,g,o of unit j (i is own value on gate-0 lane)
            float f0 = __shfl_sync(qmask, r0, lq + 1);
            float g0 = __shfl_sync(qmask, r0, lq + 2);
            float o0 = __shfl_sync(qmask, r0, lq + 3);
            float f1 = __shfl_sync(qmask, r1, lq + 1);
            float g1 = __shfl_sync(qmask, r1, lq + 2);
            float o1 = __shfl_sync(qmask, r1, lq + 3);

            if (gate == 0) {                 // owns c for unit j, both batches
                cr0 = f0 * cr0 + r0 * g0;
                cr1 = f1 * cr1 + r1 * g1;
                float h0v = o0 * uact(cr0, 2.0f * L2E, 2.0f);
                float h1v = o1 * uact(cr1, 2.0f * L2E, 2.0f);
                ((float*)hs[cur ^ 1][0])[j] = h0v;
                ((float*)hs[cur ^ 1][1])[j] = h1v;
            }
            xgc0 = xgn0;
            xgc1 = xgn1;
        }
        __syncthreads();
        cur ^= 1;
    }

    // FC head: out[b] = h_T . W_fc + b_fc   (h_T in hs[cur])
    if (tid < 2) {
        float acc = b_fc[0];
        const float* hp = (const float*)hs[cur][tid];
#pragma unroll 4
        for (int jj = 0; jj < H_; jj++) acc += hp[jj] * wfc_s[jj];
        out[batch0 + tid] = acc;
    }
}

// ---------------------------------------------------------------------------
extern "C" void kernel_launch(void* const* d_in, const int* in_sizes, int n_in,
                              void* d_out, int out_size) {
    const float* x    = (const float*)d_in[0];
    const float* h0   = (const float*)d_in[1];
    const float* c0   = (const float*)d_in[2];
    const float* W_ih = (const float*)d_in[3];
    const float* W_hh = (const float*)d_in[4];
    const float* b_ih = (const float*)d_in[5];
    const float* b_hh = (const float*)d_in[6];
    const float* W_fc = (const float*)d_in[7];
    const float* b_fc = (const float*)d_in[8];
    float* out = (float*)d_out;

    static int smem_set = 0;
    if (!smem_set) {   // host-side, idempotent attribute set (not captured)
        cudaFuncSetAttribute(xg_kernel,
                             cudaFuncAttributeMaxDynamicSharedMemorySize,
                             TT * 16 * (int)sizeof(ulonglong2));
        smem_set = 1;
    }

    dim3 grid1(T_ / TT, B_);
    xg_kernel<<<grid1, 512, TT * 16 * sizeof(ulonglong2)>>>(x, W_ih, b_ih, b_hh);

    lstm_kernel<<<B_ / 2, 416>>>(h0, c0, W_hh, W_fc, b_fc, out);
}

// round 17
// speedup vs baseline: 1.4427x; 1.4427x over previous
#include <cuda_runtime.h>
#include <cstdint>

#define B_ 256
#define T_ 1024
#define D_ 64
#define H_ 100
#define G_ 400   // 4*H
#define L2E 1.44269504088896f

#define WSTRIDE 68    // floats per row of W/x smem (pad: conflict-free frags)
#define CSTRIDE 401   // floats per t-row of C staging tile

// Precomputed input-gate contributions, PERMUTED row order:
// xg[b][t][p] holds gate-row ((p&3)*H + (p>>2)), bias included.  ~419 MB.
__device__ float g_xg[(size_t)B_ * T_ * G_];

// ---------------------------------------------------------------------------
// Helpers
// ---------------------------------------------------------------------------
__device__ __forceinline__ unsigned long long ffma2(unsigned long long a,
                                                    unsigned long long b,
                                                    unsigned long long c) {
    unsigned long long d;
    asm("fma.rn.f32x2 %0, %1, %2, %3;" : "=l"(d) : "l"(a), "l"(b), "l"(c));
    return d;
}
__device__ __forceinline__ unsigned long long pack2(float x, float y) {
    return ((unsigned long long)__float_as_uint(y) << 32) |
           (unsigned long long)__float_as_uint(x);
}
__device__ __forceinline__ float lo2(unsigned long long v) {
    return __uint_as_float((unsigned)v);
}
__device__ __forceinline__ float hi2(unsigned long long v) {
    return __uint_as_float((unsigned)(v >> 32));
}
__device__ __forceinline__ float ex2a(float x) {
    float r; asm("ex2.approx.ftz.f32 %0, %1;" : "=f"(r) : "f"(x)); return r;
}
__device__ __forceinline__ float rcpa(float x) {
    float r; asm("rcp.approx.ftz.f32 %0, %1;" : "=f"(r) : "f"(x)); return r;
}
__device__ __forceinline__ float uact(float x, float lm, float s) {
    return 1.0f - s * rcpa(ex2a(lm * x) + 1.0f);
}
__device__ __forceinline__ unsigned thi(float v) {       // exact tf32 head
    return __float_as_uint(v) & 0xFFFFE000u;
}
__device__ __forceinline__ void mma_tf32(float* c,
                                         unsigned a0, unsigned a1,
                                         unsigned a2, unsigned a3,
                                         unsigned b0, unsigned b1) {
    asm volatile(
        "mma.sync.aligned.m16n8k8.row.col.f32.tf32.tf32.f32 "
        "{%0,%1,%2,%3}, {%4,%5,%6,%7}, {%8,%9}, {%0,%1,%2,%3};"
        : "+f"(c[0]), "+f"(c[1]), "+f"(c[2]), "+f"(c[3])
        : "r"(a0), "r"(a1), "r"(a2), "r"(a3), "r"(b0), "r"(b1));
}

// ---------------------------------------------------------------------------
// Kernel 1 (tensor): xg tile C[400, 64t] = W_ih[400,64] @ x_tile^T, 3-pass
// split-tf32 (Ahi.Bhi + Ahi.Blo + Alo.Bhi) for fp32-grade accuracy.
// 800 threads = 25 warps; warp w owns rows [16w,16w+16) x all 64 t.
// Frags loaded from padded smem (stride 68: banks 4*gid+tig, conflict-free).
// C staged via smem (reusing W region) -> coalesced perm-store with bias.
// ---------------------------------------------------------------------------
__global__ __launch_bounds__(800, 1)
void xg_kernel(const float* __restrict__ x,
               const float* __restrict__ W_ih,
               const float* __restrict__ b_ih,
               const float* __restrict__ b_hh) {
    extern __shared__ float sm[];
    float* Wsm = sm;                        // [400][WSTRIDE]
    float* Xsm = sm + 400 * WSTRIDE;        // [64][WSTRIDE]
    float* Csm = sm;                        // reuse W region: [64][CSTRIDE]
    __shared__ float bias_sm[G_];

    const int b    = blockIdx.y;
    const int t0   = blockIdx.x * 64;
    const int tid  = threadIdx.x;
    const int w    = tid >> 5;
    const int lane = tid & 31;
    const int gid  = lane >> 2;             // group 0..7
    const int tig  = lane & 3;              // thread-in-group

    // ---- prologue: W (400x64) and x tile (64x64) into padded smem ----
    {
        const float4* src = (const float4*)W_ih;        // 6400 float4
#pragma unroll
        for (int i = 0; i < 8; i++) {
            int f = tid + i * 800;
            float4 v = src[f];
            int row = f >> 4, kq = f & 15;
            *(float4*)(Wsm + row * WSTRIDE + kq * 4) = v;
        }
    }
    {
        const float4* src = (const float4*)(x + ((size_t)b * T_ + t0) * D_);
        for (int i = tid; i < 64 * 16; i += 800) {
            float4 v = src[i];
            int row = i >> 4, kq = i & 15;
            *(float4*)(Xsm + row * WSTRIDE + kq * 4) = v;
        }
    }
    if (tid < G_) {                         // bias in permuted-p order
        int row = (tid & 3) * H_ + (tid >> 2);
        bias_sm[tid] = b_ih[row] + b_hh[row];
    }
    __syncthreads();

    // ---- mainloop ----
    float acc[8][4];
#pragma unroll
    for (int j = 0; j < 8; j++)
#pragma unroll
        for (int q = 0; q < 4; q++) acc[j][q] = 0.0f;

    const int arow = 16 * w + gid;
#pragma unroll
    for (int kc = 0; kc < 8; kc++) {
        const int k0 = kc * 8 + tig;
        float ar0 = Wsm[arow * WSTRIDE + k0];
        float ar1 = Wsm[(arow + 8) * WSTRIDE + k0];
        float ar2 = Wsm[arow * WSTRIDE + k0 + 4];
        float ar3 = Wsm[(arow + 8) * WSTRIDE + k0 + 4];
        unsigned ah0 = thi(ar0), ah1 = thi(ar1), ah2 = thi(ar2), ah3 = thi(ar3);
        unsigned al0 = __float_as_uint(ar0 - __uint_as_float(ah0));
        unsigned al1 = __float_as_uint(ar1 - __uint_as_float(ah1));
        unsigned al2 = __float_as_uint(ar2 - __uint_as_float(ah2));
        unsigned al3 = __float_as_uint(ar3 - __uint_as_float(ah3));
#pragma unroll
        for (int j = 0; j < 8; j++) {
            float br0 = Xsm[(8 * j + gid) * WSTRIDE + k0];
            float br1 = Xsm[(8 * j + gid) * WSTRIDE + k0 + 4];
            unsigned bh0 = thi(br0), bh1 = thi(br1);
            unsigned bl0 = __float_as_uint(br0 - __uint_as_float(bh0));
            unsigned bl1 = __float_as_uint(br1 - __uint_as_float(bh1));
            mma_tf32(acc[j], ah0, ah1, ah2, ah3, bh0, bh1);
            mma_tf32(acc[j], ah0, ah1, ah2, ah3, bl0, bl1);
            mma_tf32(acc[j], al0, al1, al2, al3, bh0, bh1);
        }
    }
    __syncthreads();                        // done reading Wsm

    // ---- scatter fragments into C staging tile [t][p] ----
    const int r0 = arow, r1 = arow + 8;
    const int p0 = (r0 % H_) * 4 + r0 / H_;
    const int p1 = (r1 % H_) * 4 + r1 / H_;
#pragma unroll
    for (int j = 0; j < 8; j++) {
        int tl = 8 * j + 2 * tig;
        Csm[tl * CSTRIDE + p0]       = acc[j][0];
        Csm[(tl + 1) * CSTRIDE + p0] = acc[j][1];
        Csm[tl * CSTRIDE + p1]       = acc[j][2];
        Csm[(tl + 1) * CSTRIDE + p1] = acc[j][3];
    }
    __syncthreads();

    // ---- coalesced store with bias ----
    float* outb = g_xg + ((size_t)b * T_ + t0) * G_;
#pragma unroll
    for (int it = 0; it < 32; it++) {       // 64*400/800 = 32
        int i = tid + it * 800;
        int t = i / G_, p = i - t * G_;
        outb[(size_t)t * G_ + p] = Csm[t * CSTRIDE + p] + bias_sm[p];
    }
}

// ---------------------------------------------------------------------------
// Kernel 2: recurrence — R13 version VERBATIM (best measured: 1.100 ms).
// ---------------------------------------------------------------------------
__global__ __launch_bounds__(416, 1)
void lstm_kernel(const float* __restrict__ h0,
                 const float* __restrict__ c0,
                 const float* __restrict__ W_hh,
                 const float* __restrict__ W_fc,
                 const float* __restrict__ b_fc,
                 float* __restrict__ out) {
    __shared__ ulonglong2 hs[2][25];     // 2 x 100 floats (h per batch row)
    __shared__ float gbuf[2][G_];        // activated gates (permuted rows)
    __shared__ float wfc_s[H_];

    const int tid    = threadIdx.x;
    const int batch0 = blockIdx.x * 2;

    float c = 0.0f;
    if (tid < 2 * H_) {
        const int b = tid / H_, j = tid - b * H_;
        ((float*)hs[b])[j] = h0[(size_t)(batch0 + b) * H_ + j];
        c = c0[(size_t)(batch0 + b) * H_ + j];
    }
    if (tid < H_) wfc_s[tid] = W_fc[tid];

    unsigned long long w2[50];
    float lm = L2E, sc = 1.0f;           // sigmoid consts
    if (tid < G_) {
        const int gate = tid & 3;
        const int row  = gate * H_ + (tid >> 2);
        const float4* wrow = (const float4*)(W_hh + (size_t)row * H_);
#pragma unroll
        for (int i = 0; i < 25; i++) {
            float4 v = wrow[i];
            w2[2 * i]     = pack2(v.x, v.y);
            w2[2 * i + 1] = pack2(v.z, v.w);
        }
        if (gate == 2) { lm = 2.0f * L2E; sc = 2.0f; }
    }

    const float* xg0 = g_xg + (size_t)(batch0)     * T_ * G_ + tid;
    const float* xg1 = g_xg + (size_t)(batch0 + 1) * T_ * G_ + tid;
    float xgc0 = 0.0f, xgc1 = 0.0f;
    if (tid < G_) { xgc0 = xg0[0]; xgc1 = xg1[0]; }

    __syncthreads();

    for (int t = 0; t < T_; t++) {
        float xgn0 = 0.0f, xgn1 = 0.0f;
        if (tid < G_ && t + 1 < T_) {
            xgn0 = xg0[(size_t)(t + 1) * G_];
            xgn1 = xg1[(size_t)(t + 1) * G_];
        }

        if (tid < G_) {
            unsigned long long a0 = 0ull, a1 = 0ull, b0 = 0ull, b1 = 0ull;
#pragma unroll
            for (int i = 0; i < 25; i++) {
                ulonglong2 hv = hs[0][i];          // broadcast LDS.128
                a0 = ffma2(w2[2 * i],     hv.x, a0);
                a1 = ffma2(w2[2 * i + 1], hv.y, a1);
            }
#pragma unroll
            for (int i = 0; i < 25; i++) {
                ulonglong2 hv = hs[1][i];
                b0 = ffma2(w2[2 * i],     hv.x, b0);
                b1 = ffma2(w2[2 * i + 1], hv.y, b1);
            }
            float acc0 = lo2(a0) + hi2(a0) + lo2(a1) + hi2(a1) + xgc0;
            float acc1 = lo2(b0) + hi2(b0) + lo2(b1) + hi2(b1) + xgc1;

            // branch-free uniform activation (sigmoid / tanh via consts)
            gbuf[0][tid] = uact(acc0, lm, sc);
            gbuf[1][tid] = uact(acc1, lm, sc);
        }
        __syncthreads();

        // phase B: gates of unit j are at gbuf[b][4j..4j+3] = one LDS.128
        if (tid < 2 * H_) {
            const int b = tid / H_, j = tid - b * H_;
            float4 g4 = *(const float4*)&gbuf[b][4 * j];   // {i,f,g,o}
            c = g4.y * c + g4.x * g4.z;
            ((float*)hs[b])[j] = g4.w * uact(c, 2.0f * L2E, 2.0f);
        }
        xgc0 = xgn0;
        xgc1 = xgn1;
        __syncthreads();
    }

    if (tid < 2) {
        float acc = b_fc[0];
        const float* hp = (const float*)hs[tid];
#pragma unroll 4
        for (int j = 0; j < H_; j++) acc += hp[j] * wfc_s[j];
        out[batch0 + tid] = acc;
    }
}

// ---------------------------------------------------------------------------
extern "C" void kernel_launch(void* const* d_in, const int* in_sizes, int n_in,
                              void* d_out, int out_size) {
    const float* x    = (const float*)d_in[0];
    const float* h0   = (const float*)d_in[1];
    const float* c0   = (const float*)d_in[2];
    const float* W_ih = (const float*)d_in[3];
    const float* W_hh = (const float*)d_in[4];
    const float* b_ih = (const float*)d_in[5];
    const float* b_hh = (const float*)d_in[6];
    const float* W_fc = (const float*)d_in[7];
    const float* b_fc = (const float*)d_in[8];
    float* out = (float*)d_out;

    const int xg_smem = (400 * WSTRIDE + 64 * WSTRIDE) * (int)sizeof(float);
    static int smem_set = 0;
    if (!smem_set) {   // host-side, idempotent attribute set (not captured)
        cudaFuncSetAttribute(xg_kernel,
                             cudaFuncAttributeMaxDynamicSharedMemorySize,
                             xg_smem);
        smem_set = 1;
    }

    dim3 grid1(T_ / 64, B_);
    xg_kernel<<<grid1, 800, xg_smem>>>(x, W_ih, b_ih, b_hh);

    lstm_kernel<<<B_ / 2, 416>>>(h0, c0, W_hh, W_fc, b_fc, out);
}